// round 8
// baseline (speedup 1.0000x reference)
#include <cuda_runtime.h>
#include <cstdint>

// AntisymmetricRNN: x_{t+1} = x_t + 0.01*tanh(A x_t + by)
// A = triu(W,1) - triu(W,1)^T - eps*I.  N=256, BS=256, TMAX=1000.
// R8: 2-CTA clusters (64 clusters x 2 CTAs = 128 CTAs). Each CTA: 128 rows x
// 256 cols of A ENTIRELY in registers (zero A-smem traffic, which bound R1-R7),
// 4 batch columns per cluster. Row-halves exchanged per step via DSMEM stores +
// per-parity mbarriers (no __syncthreads in the loop). Skewed x layout (R7),
// warp butterfly reduce (R5), fast tanh via ex2/rcp approx.

constexpr int   Nn      = 256;
constexpr int   Tmax    = 1000;
constexpr float STEPF   = 0.01f;
constexpr float EPSF    = 0.001f;
constexpr int   THREADS = 512;
constexpr int   CH      = 36;             // skewed 32-float chunk stride
constexpr int   COLSTR  = 8 * CH + 8;     // 296 floats per batch column
constexpr int   XBUF    = 4 * COLSTR;     // 4 columns per buffer

__device__ __forceinline__ void fma2(unsigned long long& d,
                                     unsigned long long a,
                                     unsigned long long b) {
    asm("fma.rn.f32x2 %0, %1, %2, %0;" : "+l"(d) : "l"(a), "l"(b));
}
__device__ __forceinline__ unsigned long long pk2(float lo, float hi) {
    unsigned long long v;
    asm("mov.b64 %0, {%1, %2};" : "=l"(v) : "f"(lo), "f"(hi));
    return v;
}
__device__ __forceinline__ float2 upk2(unsigned long long v) {
    float2 r;
    asm("mov.b64 {%0, %1}, %2;" : "=f"(r.x), "=f"(r.y) : "l"(v));
    return r;
}
__device__ __forceinline__ float aval(const float* __restrict__ W, int i, int j) {
    if (j > i) return W[i * Nn + j];
    if (j < i) return -W[j * Nn + i];
    return -EPSF;
}
__device__ __forceinline__ int xidx(int col, int row) {
    return col * COLSTR + (row >> 5) * CH + (row & 31);
}
__device__ __forceinline__ uint32_t s2u(const void* p) {
    return (uint32_t)__cvta_generic_to_shared(p);
}
__device__ __forceinline__ uint32_t mapa_u32(uint32_t addr, uint32_t r) {
    uint32_t o;
    asm("mapa.shared::cluster.u32 %0, %1, %2;" : "=r"(o) : "r"(addr), "r"(r));
    return o;
}
__device__ __forceinline__ void mbar_wait(uint32_t mb, uint32_t par) {
    uint32_t done;
    do {
        asm volatile(
            "{\n\t.reg .pred p;\n\t"
            "mbarrier.try_wait.parity.acquire.cta.shared::cta.b64 p, [%1], %2, 0x989680;\n\t"
            "selp.b32 %0, 1, 0, p;\n\t}"
            : "=r"(done) : "r"(mb), "r"(par) : "memory");
    } while (!done);
}
// tanh(y) = 1 - 2/(exp(2y)+1), via ex2.approx + rcp.approx (inf-safe)
__device__ __forceinline__ float fast_tanh(float y) {
    float e, r;
    asm("ex2.approx.ftz.f32 %0, %1;" : "=f"(e) : "f"(y * 2.8853900817779268f));
    asm("rcp.approx.ftz.f32 %0, %1;" : "=f"(r) : "f"(e + 1.0f));
    return fmaf(-2.0f, r, 1.0f);
}

__global__ void __launch_bounds__(THREADS, 1) __cluster_dims__(2, 1, 1)
antisym_rnn_kernel(const float* __restrict__ X0,
                   const float* __restrict__ W,
                   const float* __restrict__ by,
                   float* __restrict__ out) {
    __shared__ alignas(16) float sx[2][XBUF];           // double-buffered state
    __shared__ alignas(8)  unsigned long long mbar[2];  // per-parity barriers

    const int tid  = threadIdx.x;
    const int w    = tid >> 5;
    const int lane = tid & 31;
    const int kc   = lane & 7;          // col-chunk: x cols [32kc, 32kc+32)
    const int g    = lane >> 3;
    const int rg   = w * 4 + g;         // row-group 0..63 -> local rows 2rg, 2rg+1
    const int j0   = kc * 32;

    uint32_t rank;
    asm("mov.u32 %0, %%cluster_ctarank;" : "=r"(rank));
    const int cid   = blockIdx.x >> 1;  // cluster id -> batch cols 4cid..4cid+3
    const int rbase = (int)rank << 7;   // this CTA's global row base

    // reduction ownership: lane kc ends holding idx p8 = col*2 + rbit
    const int p8       = kc;
    const int col_out  = p8 >> 1;                 // 0..3
    const int grow_out = rbase + 2 * rg + (p8 & 1);
    const int lb0 = lane & 1, lb1 = (lane >> 1) & 1, lb2 = (lane >> 2) & 1;
    const int ownidx = xidx(col_out, grow_out);

    // ---- mbarrier init ----
    if (tid == 0) {
        uint32_t m0 = s2u(&mbar[0]), m1 = s2u(&mbar[1]);
        asm volatile("mbarrier.init.shared.b64 [%0], %1;" :: "r"(m0), "r"(2 * THREADS) : "memory");
        asm volatile("mbarrier.init.shared.b64 [%0], %1;" :: "r"(m1), "r"(2 * THREADS) : "memory");
    }

    // ---- precomputed shared addresses (local + peer via mapa) ----
    const uint32_t peer = rank ^ 1u;
    const uint32_t mb_l[2]  = { s2u(&mbar[0]), s2u(&mbar[1]) };
    const uint32_t mb_p[2]  = { mapa_u32(mb_l[0], peer), mapa_u32(mb_l[1], peer) };
    const uint32_t own_l[2] = { s2u(&sx[0][ownidx]), s2u(&sx[1][ownidx]) };
    const uint32_t own_p[2] = { mapa_u32(own_l[0], peer), mapa_u32(own_l[1], peer) };

    // ---- initial state: full x (all 4 cols, all 256 rows) into local buf 0 ----
    for (int q = tid; q < 4 * Nn; q += THREADS) {
        const int c = q >> 8, row = q & 255;
        sx[0][xidx(c, row)] = X0[(size_t)(4 * cid + c) * Nn + row];
    }

    // ---- per-lane persistent state + t=0 output ----
    float x_own        = X0[(size_t)(4 * cid + col_out) * Nn + grow_out];
    const float by_own = by[grow_out];
    float* outp = out + ((size_t)(4 * cid + col_out) * Tmax) * Nn + grow_out;
    outp[0] = x_own;

    // ---- A block in registers: 2 rows x 16 pairs (32 cols) per thread ----
    unsigned long long areg[2][16];
#pragma unroll
    for (int r = 0; r < 2; ++r) {
        const int row = rbase + 2 * rg + r;
#pragma unroll
        for (int p = 0; p < 16; ++p) {
            const int j = j0 + 2 * p;
            areg[r][p] = pk2(aval(W, row, j), aval(W, row, j + 1));
        }
    }

    // cluster-wide: mbar init + buf0 visible everywhere
    asm volatile("barrier.cluster.arrive.aligned;" ::: "memory");
    asm volatile("barrier.cluster.wait.aligned;" ::: "memory");

    int ph[2] = {0, 0};
    for (int s = 1; s < Tmax; ++s) {
        const int rp = (s - 1) & 1;     // read buffer
        const int wb = s & 1;           // write buffer

        if (s > 1) {
            mbar_wait(mb_l[rp], ph[rp]);
            ph[rp] ^= 1;
            asm volatile("fence.acq_rel.cluster;" ::: "memory");
        }

        const float* xp = &sx[rp][kc * CH];

        unsigned long long acc[8];      // idx = col*2 + rbit
#pragma unroll
        for (int i = 0; i < 8; ++i) acc[i] = 0ULL;

#pragma unroll
        for (int pi = 0; pi < 8; ++pi) {
            const ulonglong2 q0 = *reinterpret_cast<const ulonglong2*>(xp + 0 * COLSTR + 4 * pi);
            const ulonglong2 q1 = *reinterpret_cast<const ulonglong2*>(xp + 1 * COLSTR + 4 * pi);
            const ulonglong2 q2 = *reinterpret_cast<const ulonglong2*>(xp + 2 * COLSTR + 4 * pi);
            const ulonglong2 q3 = *reinterpret_cast<const ulonglong2*>(xp + 3 * COLSTR + 4 * pi);
#pragma unroll
            for (int r = 0; r < 2; ++r) {
                fma2(acc[0 + r], areg[r][2 * pi], q0.x); fma2(acc[0 + r], areg[r][2 * pi + 1], q0.y);
                fma2(acc[2 + r], areg[r][2 * pi], q1.x); fma2(acc[2 + r], areg[r][2 * pi + 1], q1.y);
                fma2(acc[4 + r], areg[r][2 * pi], q2.x); fma2(acc[4 + r], areg[r][2 * pi + 1], q2.y);
                fma2(acc[6 + r], areg[r][2 * pi], q3.x); fma2(acc[6 + r], areg[r][2 * pi + 1], q3.y);
            }
        }

        float v[8];
#pragma unroll
        for (int i = 0; i < 8; ++i) {
            const float2 f = upk2(acc[i]);
            v[i] = f.x + f.y;
        }

        // 3-round butterfly across the 8-lane kc group: lane p8 ends with sum of v[p8]
        float u[4];
#pragma unroll
        for (int k = 0; k < 4; ++k) {
            const float keep = lb0 ? v[2 * k + 1] : v[2 * k];
            const float send = lb0 ? v[2 * k]     : v[2 * k + 1];
            u[k] = keep + __shfl_xor_sync(0xFFFFFFFFu, send, 1);
        }
        float w2[2];
#pragma unroll
        for (int m = 0; m < 2; ++m) {
            const float keep = lb1 ? u[2 * m + 1] : u[2 * m];
            const float send = lb1 ? u[2 * m]     : u[2 * m + 1];
            w2[m] = keep + __shfl_xor_sync(0xFFFFFFFFu, send, 2);
        }
        {
            const float keep = lb2 ? w2[1] : w2[0];
            const float send = lb2 ? w2[0] : w2[1];
            const float y = keep + __shfl_xor_sync(0xFFFFFFFFu, send, 4) + by_own;
            x_own += STEPF * fast_tanh(y);
        }

        outp[(size_t)s * Nn] = x_own;

        if (s < Tmax - 1) {
            // publish x_own to both CTAs' buf[wb]
            asm volatile("st.shared.f32 [%0], %1;" :: "r"(own_l[wb]), "f"(x_own) : "memory");
            asm volatile("st.shared::cluster.f32 [%0], %1;" :: "r"(own_p[wb]), "f"(x_own) : "memory");
            asm volatile("fence.acq_rel.cluster;" ::: "memory");
            asm volatile("mbarrier.arrive.shared.b64 _, [%0];" :: "r"(mb_l[wb]) : "memory");
            asm volatile("mbarrier.arrive.shared::cluster.b64 _, [%0];" :: "r"(mb_p[wb]) : "memory");
        }
    }

    // no CTA may exit while peer DSMEM traffic may be in flight
    asm volatile("barrier.cluster.arrive.aligned;" ::: "memory");
    asm volatile("barrier.cluster.wait.aligned;" ::: "memory");
}

extern "C" void kernel_launch(void* const* d_in, const int* in_sizes, int n_in,
                              void* d_out, int out_size) {
    const float* X0 = (const float*)d_in[0];
    const float* W  = (const float*)d_in[1];
    const float* by = (const float*)d_in[2];
    float* out      = (float*)d_out;

    antisym_rnn_kernel<<<128, THREADS>>>(X0, W, by, out);
}

// round 14
// speedup vs baseline: 1.2787x; 1.2787x over previous
#include <cuda_runtime.h>
#include <cstdint>

// AntisymmetricRNN: x_{t+1} = x_t + 0.01*tanh(A x_t + by)
// A = triu(W,1) - triu(W,1)^T - eps*I.  N=256, BS=256, TMAX=1000.
// R10: exploit antisymmetry -- only the unique strict-upper triangle of A
// (128 KB) is stored, ENTIRELY in registers (forward + transposed use of each
// coefficient). Zero per-step A-smem traffic (the binder of R1-R7).
// 128 CTAs x 2 batch cols, 512 threads:
//   warps 0-14: 120 off-diag 16x16 tiles, 4-lane teams (4 rows x 16 cols each),
//               fwd + transp; transp partials combined via 2-round shfl butterfly.
//   warp 15:    16 diagonal tiles (full 16x16 incl. sign/-eps), fwd only,
//               streamed from a lane-major (conflict-free) smem image.
// Uniform fan-in 16 partial slots per output; 2 barriers/step; fast tanh.

constexpr int   Nn      = 256;
constexpr int   Tmax    = 1000;
constexpr float STEPF   = 0.01f;
constexpr float EPSF    = 0.001f;
constexpr int   THREADS = 512;

constexpr int   GSTR    = 20;              // x group stride (16 data + 4 pad floats)
constexpr int   XCS     = 16 * GSTR + 16;  // 336: x col stride (floats)
constexpr int   PSS     = 272;             // partial slot stride (floats)
constexpr int   PCS     = 16 * PSS;        // 4352: partial col stride

constexpr int   OFF_X    = 0;                    // 2*336 = 672 floats
constexpr int   OFF_PART = 672;                  // 2*16*272 = 8704 floats
constexpr int   OFF_DIAG = 672 + 8704;           // 9376 ; 32 chunks * 32 lanes * 4 floats
constexpr int   SM_FLOATS = OFF_DIAG + 4096;     // 13472 floats = 53888 B

__device__ __forceinline__ void fma2(unsigned long long& d,
                                     unsigned long long a,
                                     unsigned long long b) {
    asm("fma.rn.f32x2 %0, %1, %2, %0;" : "+l"(d) : "l"(a), "l"(b));
}
__device__ __forceinline__ unsigned long long pk2(float lo, float hi) {
    unsigned long long v;
    asm("mov.b64 %0, {%1, %2};" : "=l"(v) : "f"(lo), "f"(hi));
    return v;
}
__device__ __forceinline__ float2 upk2(unsigned long long v) {
    float2 r;
    asm("mov.b64 {%0, %1}, %2;" : "=f"(r.x), "=f"(r.y) : "l"(v));
    return r;
}
__device__ __forceinline__ unsigned long long addx2(unsigned long long a,
                                                    unsigned long long b) {
    unsigned long long d;
    asm("add.rn.f32x2 %0, %1, %2;" : "=l"(d) : "l"(a), "l"(b));
    return d;
}
__device__ __forceinline__ float aval(const float* __restrict__ W, int i, int j) {
    if (j > i) return W[i * Nn + j];
    if (j < i) return -W[j * Nn + i];
    return -EPSF;
}
// tanh(y) = 1 - 2/(exp(2y)+1)  (inf-safe; ~1e-7 rel)
__device__ __forceinline__ float fast_tanh(float y) {
    float e, r;
    asm("ex2.approx.ftz.f32 %0, %1;" : "=f"(e) : "f"(y * 2.8853900817779268f));
    asm("rcp.approx.ftz.f32 %0, %1;" : "=f"(r) : "f"(e + 1.0f));
    return fmaf(-2.0f, r, 1.0f);
}

__global__ void __launch_bounds__(THREADS, 1)
antisym_rnn_kernel(const float* __restrict__ X0,
                   const float* __restrict__ W,
                   const float* __restrict__ by,
                   float* __restrict__ out) {
    extern __shared__ float sm[];
    float* xs   = sm + OFF_X;
    float* part = sm + OFF_PART;
    float* dga  = sm + OFF_DIAG;

    const int tid  = threadIdx.x;
    const int lane = tid & 31;
    const int bid  = blockIdx.x;

    // ---- finalize identity: thread k owns output (col k>>8, row k&255) ----
    const int c_out   = tid >> 8;
    const int row_out = tid & 255;
    const float byv   = by[row_out];
    float x_own       = X0[(size_t)(2 * bid + c_out) * Nn + row_out];
    float* outp       = out + ((size_t)(2 * bid + c_out) * Tmax) * Nn + row_out;
    outp[0] = x_own;
    xs[c_out * XCS + (row_out >> 4) * GSTR + (row_out & 15)] = x_own;

    // ---- diagonal-tile A image, lane-major (conflict-free stream) ----
    // chunk ch=r*4+h (r=row 0..7 within sub, h=4-col chunk), lane ln -> (tile d=ln>>1, sub s=ln&1)
    for (int idx = tid; idx < 1024; idx += THREADS) {
        const int ch = idx >> 5, ln = idx & 31;
        const int d = ln >> 1, s5 = ln & 1;
        const int r = ch >> 2, h = ch & 3;
        const int i  = d * 16 + 8 * s5 + r;
        const int jb = d * 16 + 4 * h;
        float4 v;
        v.x = aval(W, i, jb);     v.y = aval(W, i, jb + 1);
        v.z = aval(W, i, jb + 2); v.w = aval(W, i, jb + 3);
        *reinterpret_cast<float4*>(dga + (ch * 32 + ln) * 4) = v;
    }

    // ---- off-diag tile assignment (scattered to decorrelate banks) ----
    const bool offd = tid < 480;
    int a = 0, b = 0, q = 0;
    unsigned long long A[4][8];
    if (offd) {
        q = tid & 3;
        int rem = ((tid >> 2) * 17) % 120;     // permuted tile index
        while (rem >= 15 - a) { rem -= 15 - a; ++a; }
        b = a + 1 + rem;
#pragma unroll
        for (int r = 0; r < 4; ++r) {
            const int i = a * 16 + 4 * q + r;
#pragma unroll
            for (int p = 0; p < 8; ++p) {
                const int j = b * 16 + 2 * p;
                A[r][p] = pk2(W[i * Nn + j], W[i * Nn + j + 1]);   // i<j: strictly upper
            }
        }
    }
    const int dtl = (tid - 480) >> 1;   // diag tile (warp 15 only)
    const int ds  = tid & 1;            // diag sub-rows

    __syncthreads();

    // ================= time loop =================
    for (int s = 1; s < Tmax; ++s) {
        if (offd) {
#pragma unroll
            for (int c = 0; c < 2; ++c) {
                const float* xc = xs + c * XCS;
                const ulonglong2* xbp = reinterpret_cast<const ulonglong2*>(xc + b * GSTR);
                const ulonglong2 xq0 = xbp[0], xq1 = xbp[1], xq2 = xbp[2], xq3 = xbp[3];
                const float4 xo = *reinterpret_cast<const float4*>(xc + a * GSTR + 4 * q);

                unsigned long long accF[4] = {0ULL, 0ULL, 0ULL, 0ULL};
                unsigned long long accT[8] = {0ULL, 0ULL, 0ULL, 0ULL, 0ULL, 0ULL, 0ULL, 0ULL};

                // forward: y_i += sum_j T_ij x_j   (rows a*16+4q+r, cols group b)
#pragma unroll
                for (int r = 0; r < 4; ++r) {
                    fma2(accF[r], A[r][0], xq0.x); fma2(accF[r], A[r][1], xq0.y);
                    fma2(accF[r], A[r][2], xq1.x); fma2(accF[r], A[r][3], xq1.y);
                    fma2(accF[r], A[r][4], xq2.x); fma2(accF[r], A[r][5], xq2.y);
                    fma2(accF[r], A[r][6], xq3.x); fma2(accF[r], A[r][7], xq3.y);
                }
                // transpose: y_j -= sum_i T_ij x_i  (cols group b get -T^T x)
                {
                    const float xr[4] = {xo.x, xo.y, xo.z, xo.w};
#pragma unroll
                    for (int r = 0; r < 4; ++r) {
                        const unsigned long long nx = pk2(-xr[r], -xr[r]);
#pragma unroll
                        for (int p = 0; p < 8; ++p) fma2(accT[p], A[r][p], nx);
                    }
                }

                // forward partials: rows a*16+4q..+3, slot b
                float4 fs;
                { float2 f = upk2(accF[0]); fs.x = f.x + f.y; }
                { float2 f = upk2(accF[1]); fs.y = f.x + f.y; }
                { float2 f = upk2(accF[2]); fs.z = f.x + f.y; }
                { float2 f = upk2(accF[3]); fs.w = f.x + f.y; }
                *reinterpret_cast<float4*>(part + c * PCS + b * PSS + a * 16 + 4 * q) = fs;

                // transpose partials: combine across 4-lane team, then lane q stores chunk q
#pragma unroll
                for (int p = 0; p < 8; ++p) {
                    accT[p] = addx2(accT[p], __shfl_xor_sync(0xFFFFFFFFu, accT[p], 1));
                    accT[p] = addx2(accT[p], __shfl_xor_sync(0xFFFFFFFFu, accT[p], 2));
                }
                ulonglong2 ts;
                ts.x = accT[2 * q]; ts.y = accT[2 * q + 1];
                *reinterpret_cast<ulonglong2*>(part + c * PCS + a * PSS + b * 16 + 4 * q) = ts;
            }
        } else {
            // warp 15: diagonal tiles, forward-only from lane-major smem image
#pragma unroll
            for (int c = 0; c < 2; ++c) {
                const float* xc = xs + c * XCS;
                const ulonglong2* xbp = reinterpret_cast<const ulonglong2*>(xc + dtl * GSTR);
                const ulonglong2 xq[4] = {xbp[0], xbp[1], xbp[2], xbp[3]};
                float sd[8];
#pragma unroll
                for (int r = 0; r < 8; ++r) {
                    unsigned long long acc = 0ULL;
#pragma unroll
                    for (int h = 0; h < 4; ++h) {
                        const ulonglong2 A2 = *reinterpret_cast<const ulonglong2*>(
                            dga + ((r * 4 + h) * 32 + lane) * 4);
                        fma2(acc, A2.x, xq[h].x);
                        fma2(acc, A2.y, xq[h].y);
                    }
                    const float2 f = upk2(acc);
                    sd[r] = f.x + f.y;
                }
                float* pb = part + c * PCS + dtl * PSS + dtl * 16 + 8 * ds;
                *reinterpret_cast<float4*>(pb)     = make_float4(sd[0], sd[1], sd[2], sd[3]);
                *reinterpret_cast<float4*>(pb + 4) = make_float4(sd[4], sd[5], sd[6], sd[7]);
            }
        }
        __syncthreads();

        // ---- finalize: every thread one output; fan-in 16 slots ----
        {
            const float* pp = part + c_out * PCS + row_out;
            float y0 = byv, y1 = 0.f, y2 = 0.f, y3 = 0.f;
#pragma unroll
            for (int sl = 0; sl < 16; sl += 4) {
                y0 += pp[(sl + 0) * PSS];
                y1 += pp[(sl + 1) * PSS];
                y2 += pp[(sl + 2) * PSS];
                y3 += pp[(sl + 3) * PSS];
            }
            const float y = (y0 + y1) + (y2 + y3);
            x_own += STEPF * fast_tanh(y);
            outp[(size_t)s * Nn] = x_own;
            xs[c_out * XCS + (row_out >> 4) * GSTR + (row_out & 15)] = x_own;
        }
        __syncthreads();
    }
}

extern "C" void kernel_launch(void* const* d_in, const int* in_sizes, int n_in,
                              void* d_out, int out_size) {
    const float* X0 = (const float*)d_in[0];
    const float* W  = (const float*)d_in[1];
    const float* by = (const float*)d_in[2];
    float* out      = (float*)d_out;

    const int smem_bytes = SM_FLOATS * 4;
    cudaFuncSetAttribute(antisym_rnn_kernel,
                         cudaFuncAttributeMaxDynamicSharedMemorySize, smem_bytes);
    antisym_rnn_kernel<<<128, THREADS, smem_bytes>>>(X0, W, by, out);
}

// round 15
// speedup vs baseline: 1.8185x; 1.4221x over previous
#include <cuda_runtime.h>
#include <cstdint>

// AntisymmetricRNN: x_{t+1} = x_t + 0.01*tanh(A x_t + by)
// A = triu(W,1) - triu(W,1)^T - eps*I.  N=256, BS=256, TMAX=1000.
// R15: uniform triangle scheme. T = triu(W,1) tiled into 136 16x16 tiles
// (a<=b): 120 dense off-diag + 16 strict-upper diag. 136 teams of 4 lanes
// (544 threads), each team holds its tile ENTIRELY in registers (32 f32x2 =
// 64 regs) and computes fwd (rows a, slot b) + negated-transpose (rows b,
// slot a; diag -> slot 16). Every output sums exactly 17 slots; -eps*x and
// +by folded into finalize via register-resident x_own. x in smem with
// GSTR=18 skew -> LDS.64 loads provably conflict-free. 2 barriers/step.

constexpr int   Nn      = 256;
constexpr int   Tmax    = 1000;
constexpr float STEPF   = 0.01f;
constexpr float EPSF    = 0.001f;
constexpr int   THREADS = 544;            // 136 teams x 4 lanes = 17 warps

constexpr int   GSTR    = 18;             // floats per 16-row group (skew)
constexpr int   XCS     = 16 * GSTR + 8;  // 296: x column stride
constexpr int   PSS     = 272;            // partial slot stride (256 + 16 pad)
constexpr int   PCS     = 17 * PSS;       // 4624: partial column stride

constexpr int   OFF_X     = 0;            // 2*296 = 592 floats
constexpr int   OFF_PART  = 592;          // 2*4624 = 9248 floats
constexpr int   SM_FLOATS = OFF_PART + 2 * PCS;   // 9840 floats = 39360 B

__device__ __forceinline__ void fma2(unsigned long long& d,
                                     unsigned long long a,
                                     unsigned long long b) {
    asm("fma.rn.f32x2 %0, %1, %2, %0;" : "+l"(d) : "l"(a), "l"(b));
}
__device__ __forceinline__ unsigned long long addx2(unsigned long long a,
                                                    unsigned long long b) {
    unsigned long long d;
    asm("add.rn.f32x2 %0, %1, %2;" : "=l"(d) : "l"(a), "l"(b));
    return d;
}
__device__ __forceinline__ unsigned long long pk2(float lo, float hi) {
    unsigned long long v;
    asm("mov.b64 %0, {%1, %2};" : "=l"(v) : "f"(lo), "f"(hi));
    return v;
}
__device__ __forceinline__ float2 upk2(unsigned long long v) {
    float2 r;
    asm("mov.b64 {%0, %1}, %2;" : "=f"(r.x), "=f"(r.y) : "l"(v));
    return r;
}
// strict-upper of W (zero elsewhere); -eps*I handled at finalize
__device__ __forceinline__ float tval(const float* __restrict__ W, int i, int j) {
    return (j > i) ? W[i * Nn + j] : 0.0f;
}
// tanh(y) = 1 - 2/(exp(2y)+1)  (inf-safe, ~1e-7 rel)
__device__ __forceinline__ float fast_tanh(float y) {
    float e, r;
    asm("ex2.approx.ftz.f32 %0, %1;" : "=f"(e) : "f"(y * 2.8853900817779268f));
    asm("rcp.approx.ftz.f32 %0, %1;" : "=f"(r) : "f"(e + 1.0f));
    return fmaf(-2.0f, r, 1.0f);
}

__global__ void __launch_bounds__(THREADS, 1)
antisym_rnn_kernel(const float* __restrict__ X0,
                   const float* __restrict__ W,
                   const float* __restrict__ by,
                   float* __restrict__ out) {
    extern __shared__ float sm[];
    float* xs   = sm + OFF_X;
    float* part = sm + OFF_PART;

    const int tid  = threadIdx.x;
    const int lane = tid & 31;
    const int q    = tid & 3;            // lane within team
    const int bid  = blockIdx.x;

    // ---- team -> tile (a, b), a <= b ----
    int a = 0, rem = tid >> 2;           // team id 0..135
    while (rem >= 16 - a) { rem -= 16 - a; ++a; }
    const int b = a + rem;
    const int tslot = (a == b) ? 16 : a; // transpose partial slot

    const int b0q = q & 1, b1q = (q >> 1) & 1;   // butterfly select bits

    // ---- output ownership (threads 0..511) ----
    const bool has_out = tid < 512;
    const int  c_out   = (tid >> 8) & 1;
    const int  row_out = tid & 255;
    float x_own = 0.f, byv = 0.f;
    float* outp = nullptr;
    if (has_out) {
        byv   = by[row_out];
        x_own = X0[(size_t)(2 * bid + c_out) * Nn + row_out];
        outp  = out + ((size_t)(2 * bid + c_out) * Tmax) * Nn + row_out;
        outp[0] = x_own;
        xs[c_out * XCS + (row_out >> 4) * GSTR + (row_out & 15)] = x_own;
    }

    // ---- tile block in registers: 4 rows x 8 pairs (16 cols) ----
    unsigned long long A[4][8];
#pragma unroll
    for (int r = 0; r < 4; ++r) {
        const int i = a * 16 + 4 * q + r;
#pragma unroll
        for (int p = 0; p < 8; ++p) {
            const int j = b * 16 + 2 * p;
            A[r][p] = pk2(tval(W, i, j), tval(W, i, j + 1));
        }
    }
    __syncthreads();

    // ================= time loop =================
    for (int s = 1; s < Tmax; ++s) {
#pragma unroll
        for (int c = 0; c < 2; ++c) {
            const float* xc = xs + c * XCS;

            // ---- forward: rows a*16+4q+r += T(a,b) * x[group b] ----
            unsigned long long xq[8];
#pragma unroll
            for (int m8 = 0; m8 < 8; ++m8)
                xq[m8] = *reinterpret_cast<const unsigned long long*>(xc + b * GSTR + 2 * m8);

            unsigned long long accF[4] = {0ULL, 0ULL, 0ULL, 0ULL};
#pragma unroll
            for (int p = 0; p < 8; ++p) {
#pragma unroll
                for (int r = 0; r < 4; ++r) fma2(accF[r], A[r][p], xq[p]);
            }
            float4 fs;
            { const float2 f = upk2(accF[0]); fs.x = f.x + f.y; }
            { const float2 f = upk2(accF[1]); fs.y = f.x + f.y; }
            { const float2 f = upk2(accF[2]); fs.z = f.x + f.y; }
            { const float2 f = upk2(accF[3]); fs.w = f.x + f.y; }
            *reinterpret_cast<float4*>(part + c * PCS + b * PSS + a * 16 + 4 * q) = fs;

            // ---- transpose: cols group b -= T(a,b)^T * x[rows a] ----
            const unsigned long long xo01 =
                *reinterpret_cast<const unsigned long long*>(xc + a * GSTR + 4 * q);
            const unsigned long long xo23 =
                *reinterpret_cast<const unsigned long long*>(xc + a * GSTR + 4 * q + 2);
            const float2 xo0 = upk2(xo01);
            const float2 xo1 = upk2(xo23);
            const float xr[4] = {xo0.x, xo0.y, xo1.x, xo1.y};

            unsigned long long accT[8] = {0ULL,0ULL,0ULL,0ULL,0ULL,0ULL,0ULL,0ULL};
#pragma unroll
            for (int r = 0; r < 4; ++r) {
                const unsigned long long nx = pk2(-xr[r], -xr[r]);
#pragma unroll
                for (int p = 0; p < 8; ++p) fma2(accT[p], A[r][p], nx);
            }

            // 2-round butterfly across the 4-lane team:
            // lane q ends with full sums of pairs {2q, 2q+1}
            unsigned long long sA[4];
#pragma unroll
            for (int k = 0; k < 4; ++k) {
                const unsigned long long keep = b1q ? accT[4 + k] : accT[k];
                const unsigned long long send = b1q ? accT[k]     : accT[4 + k];
                sA[k] = addx2(keep, __shfl_xor_sync(0xFFFFFFFFu, send, 2));
            }
            ulonglong2 ts;
            {
                const unsigned long long keep = b0q ? sA[2] : sA[0];
                const unsigned long long send = b0q ? sA[0] : sA[2];
                ts.x = addx2(keep, __shfl_xor_sync(0xFFFFFFFFu, send, 1));
            }
            {
                const unsigned long long keep = b0q ? sA[3] : sA[1];
                const unsigned long long send = b0q ? sA[1] : sA[3];
                ts.y = addx2(keep, __shfl_xor_sync(0xFFFFFFFFu, send, 1));
            }
            *reinterpret_cast<ulonglong2*>(part + c * PCS + tslot * PSS + b * 16 + 4 * q) = ts;
        }
        __syncthreads();

        // ---- finalize: 512 threads, one output each, fan-in 17 slots ----
        if (has_out) {
            const float* pp = part + c_out * PCS + row_out;
            float y0 = byv - EPSF * x_own, y1 = 0.f, y2 = 0.f, y3 = 0.f;
#pragma unroll
            for (int sl = 0; sl < 16; sl += 4) {
                y0 += pp[(sl + 0) * PSS];
                y1 += pp[(sl + 1) * PSS];
                y2 += pp[(sl + 2) * PSS];
                y3 += pp[(sl + 3) * PSS];
            }
            const float y = (y0 + y1) + (y2 + y3) + pp[16 * PSS];
            x_own += STEPF * fast_tanh(y);
            outp[(size_t)s * Nn] = x_own;
            xs[c_out * XCS + (row_out >> 4) * GSTR + (row_out & 15)] = x_own;
        }
        __syncthreads();
    }
}

extern "C" void kernel_launch(void* const* d_in, const int* in_sizes, int n_in,
                              void* d_out, int out_size) {
    const float* X0 = (const float*)d_in[0];
    const float* W  = (const float*)d_in[1];
    const float* by = (const float*)d_in[2];
    float* out      = (float*)d_out;

    const int smem_bytes = SM_FLOATS * 4;
    cudaFuncSetAttribute(antisym_rnn_kernel,
                         cudaFuncAttributeMaxDynamicSharedMemorySize, smem_bytes);
    antisym_rnn_kernel<<<128, THREADS, smem_bytes>>>(X0, W, by, out);
}